// round 11
// baseline (speedup 1.0000x reference)
#include <cuda_runtime.h>
#include <cstdint>

// Conv_39333310497378 — fp16 mma.sync; x and W pre-converted to fp16 by prep
// kernels; main kernel: double-buffered cp.async, no staging/convert phase.
// pot(b,s,o) = max_{h<4} sum_{k<240} x[b*1640 + 160s + 40h + k] * W[s,o,k]
// out: pots [B,50,9] then spikes [B,50,9] (f32), index b*450 + o*9 + s.

#define NB      16384
#define XSLAB   1640
#define THRESH  6.2f
#define NTHR    128

#define XSTRW   180        // xbuf row stride (fp16x2 words); banks 20*lr+lc distinct
#define WSTRW   124        // wbuf row stride (words); banks 28*lr+lc distinct; 496B %16==0
#define WROWS   56
#define WSEC    (WROWS * WSTRW)              // 6944 words

__device__ uint32_t g_w16[9 * WSEC];         // 250 KB  (zero-init: pad rows 50..55 = 0)
__device__ uint32_t g_x16[(size_t)NB * 820]; // 53.7 MB fp16 slab copy of x

// smem words: xbuf0 [0,5760) | xbuf1 [5760,11520) | wbuf [11520,18464)
#define XBUF_WORDS (32 * XSTRW)              // 5760
#define WB_OFF     (2 * XBUF_WORDS)
#define SMEM_BYTES ((WB_OFF + WSEC) * 4)     // 73856 -> 3 CTAs/SM

// ---------------- prep kernels ----------------
__global__ void prep_x_kernel(const float* __restrict__ x)
{
  int i = blockIdx.x * blockDim.x + threadIdx.x;   // float4 chunks
  if (i >= NB * 410) return;
  int b = i / 410, q = i - b * 410;
  float4 v = *reinterpret_cast<const float4*>(x + (size_t)b * XSLAB + 4 * q);
  uint32_t w0, w1;
  asm("cvt.rn.f16x2.f32 %0, %1, %2;" : "=r"(w0) : "f"(v.y), "f"(v.x));
  asm("cvt.rn.f16x2.f32 %0, %1, %2;" : "=r"(w1) : "f"(v.w), "f"(v.z));
  *reinterpret_cast<uint2*>(g_x16 + (size_t)b * 820 + 2 * q) = make_uint2(w0, w1);
}

__global__ void prep_w_kernel(const float* __restrict__ W)
{
  int i = blockIdx.x * blockDim.x + threadIdx.x;   // 8-float chunks
  if (i >= 9 * 50 * 30) return;
  int s = i / 1500, rem = i - s * 1500;
  int o = rem / 30,  q  = rem - o * 30;
  const float* src = W + ((size_t)(s * 50 + o) * 240 + 8 * q);
  float4 v0 = *reinterpret_cast<const float4*>(src);
  float4 v1 = *reinterpret_cast<const float4*>(src + 4);
  uint4 t;
  asm("cvt.rn.f16x2.f32 %0, %1, %2;" : "=r"(t.x) : "f"(v0.y), "f"(v0.x));
  asm("cvt.rn.f16x2.f32 %0, %1, %2;" : "=r"(t.y) : "f"(v0.w), "f"(v0.z));
  asm("cvt.rn.f16x2.f32 %0, %1, %2;" : "=r"(t.z) : "f"(v1.y), "f"(v1.x));
  asm("cvt.rn.f16x2.f32 %0, %1, %2;" : "=r"(t.w) : "f"(v1.w), "f"(v1.z));
  *reinterpret_cast<uint4*>(g_w16 + s * WSEC + o * WSTRW + 4 * q) = t;
}

// ---------------- main kernel ----------------
__device__ __forceinline__ uint32_t s2u(const void* p){
  uint32_t a;
  asm("{.reg .u64 t; cvta.to.shared.u64 t, %1; cvt.u32.u64 %0, t;}" : "=r"(a) : "l"(p));
  return a;
}
__device__ __forceinline__ void cp16(uint32_t dst, const void* src){
  asm volatile("cp.async.cg.shared.global [%0], [%1], 16;" :: "r"(dst), "l"(src) : "memory");
}

template<int JN>
__device__ __forceinline__ void core(const uint32_t* __restrict__ xb,
                                     const uint32_t* __restrict__ wb,
                                     int wm, int wn, int lr, int lc,
                                     int b0, int s, float* __restrict__ out)
{
  float d[4][JN][4];
  #pragma unroll
  for (int h = 0; h < 4; h++)
    #pragma unroll
    for (int j = 0; j < JN; j++)
      #pragma unroll
      for (int c = 0; c < 4; c++) d[h][j][c] = 0.f;

  const int ar = (wm * 16 + lr) * XSTRW + lc;
  const int wr = (wn * 32 + lr) * WSTRW + lc;

  #pragma unroll 3
  for (int ks = 0; ks < 15; ks++)
  {
    const int ko = 8 * ks;
    uint32_t b[JN][2];
    #pragma unroll
    for (int j = 0; j < JN; j++){
      b[j][0] = wb[wr + j * (8 * WSTRW) + ko];
      b[j][1] = wb[wr + j * (8 * WSTRW) + ko + 4];
    }
    uint32_t a[4][4];
    #pragma unroll
    for (int h = 0; h < 4; h++){
      int wa = ar + 20 * h + ko;
      a[h][0] = xb[wa];
      a[h][1] = xb[wa + 8 * XSTRW];
      a[h][2] = xb[wa + 4];
      a[h][3] = xb[wa + 8 * XSTRW + 4];
    }
    #pragma unroll
    for (int h = 0; h < 4; h++)
      #pragma unroll
      for (int j = 0; j < JN; j++)
        asm("mma.sync.aligned.m16n8k16.row.col.f32.f16.f16.f32 "
            "{%0,%1,%2,%3},{%4,%5,%6,%7},{%8,%9},{%0,%1,%2,%3};"
            : "+f"(d[h][j][0]), "+f"(d[h][j][1]),
              "+f"(d[h][j][2]), "+f"(d[h][j][3])
            : "r"(a[h][0]), "r"(a[h][1]), "r"(a[h][2]), "r"(a[h][3]),
              "r"(b[j][0]), "r"(b[j][1]));
  }

  #pragma unroll
  for (int j = 0; j < JN; j++)
    #pragma unroll
    for (int c = 0; c < 4; c++){
      int o = wn * 32 + 8 * j + 2 * lc + (c & 1);
      if (o < 50){
        float m = fmaxf(fmaxf(d[0][j][c], d[1][j][c]),
                        fmaxf(d[2][j][c], d[3][j][c]));
        int r = b0 + wm * 16 + lr + ((c >> 1) << 3);
        size_t base = (size_t)r * 450 + (size_t)(o * 9 + s);
        out[base]                    = m;
        out[base + (size_t)NB * 450] = (m > THRESH) ? 1.0f : 0.0f;
      }
    }
}

__global__ void __launch_bounds__(NTHR, 3)
conv_main(float* __restrict__ out)
{
  extern __shared__ uint32_t sm[];
  uint32_t* xbuf[2] = { sm, sm + XBUF_WORDS };
  uint32_t* wb      = sm + WB_OFF;

  const uint32_t xsa0 = s2u(sm);
  const uint32_t wsa  = s2u(wb);

  const int tid = threadIdx.x;
  const int warp = tid >> 5, lane = tid & 31;
  const int lr = lane >> 2, lc = lane & 3;
  const int wm = warp & 1,  wn = warp >> 1;
  const int b0 = blockIdx.x * 32;

  // x window for section s, row r: g_x16[(b0+r)*820 + 80s .. +180) — linear,
  // 16B-aligned (320s bytes). 45 chunks/row * 32 rows = 1440.
  auto load_x = [&](int s, int buf){
    const uint32_t base = xsa0 + (uint32_t)(buf * XBUF_WORDS) * 4u;
    #pragma unroll 4
    for (int i = tid; i < 1440; i += NTHR){
      int row = i / 45, c = i - row * 45;
      cp16(base + (uint32_t)(row * XSTRW + 4 * c) * 4u,
           g_x16 + (size_t)(b0 + row) * 820 + 80 * s + 4 * c);
    }
  };
  auto load_w = [&](int s){
    const uint32_t* src = g_w16 + s * WSEC;
    #pragma unroll 4
    for (int i = tid; i < WSEC / 4; i += NTHR)     // 1736 16B chunks
      cp16(wsa + 16u * (uint32_t)i, src + 4 * i);
  };

  load_x(0, 0);
  load_w(0);
  asm volatile("cp.async.commit_group;" ::: "memory");

  int cur = 0;
  for (int s = 0; s < 9; s++)
  {
    if (s < 8){                        // x(s+1) flies over compute(s)
      load_x(s + 1, cur ^ 1);
      asm volatile("cp.async.commit_group;" ::: "memory");
      asm volatile("cp.async.wait_group 1;" ::: "memory");
    } else {
      asm volatile("cp.async.wait_group 0;" ::: "memory");
    }
    __syncthreads();                   // xbuf[cur] + wbuf(s) visible

    if (wn == 0) core<4>(xbuf[cur], wb, wm, 0, lr, lc, b0, s, out);
    else         core<3>(xbuf[cur], wb, wm, 1, lr, lc, b0, s, out);

    __syncthreads();                   // wbuf consumed by all warps
    if (s < 8){
      load_w(s + 1);
      asm volatile("cp.async.commit_group;" ::: "memory");
    }
    cur ^= 1;
  }
}

extern "C" void kernel_launch(void* const* d_in, const int* in_sizes, int n_in,
                              void* d_out, int out_size)
{
  const float* x = (const float*)d_in[0];
  const float* W = (const float*)d_in[1];
  if (n_in >= 2 && in_sizes[0] < in_sizes[1]) {
    x = (const float*)d_in[1];
    W = (const float*)d_in[0];
  }
  float* out = (float*)d_out;

  prep_x_kernel<<<(NB * 410 + 255) / 256, 256>>>(x);   // 6.7M float4 chunks
  prep_w_kernel<<<54, 256>>>(W);

  cudaFuncSetAttribute(conv_main,
                       cudaFuncAttributeMaxDynamicSharedMemorySize, SMEM_BYTES);
  conv_main<<<NB / 32, NTHR, SMEM_BYTES>>>(out);
}